// round 15
// baseline (speedup 1.0000x reference)
#include <cuda_runtime.h>
#include <cuda_bf16.h>
#include <math.h>
#include <cstdint>

// ContrastiveLossSimCLR via mma.sync bf16 HMMA, exploiting s_pp symmetry.
//   zp = normalize(pred), zq = normalize(positive)   [fp32 math, stored bf16]
//   neg_i = sum_m exp(2*zp_i.zp_m) - exp(2) + sum_m exp(2*zp_i.zq_m)
//   loss  = mean_i( log(neg_i) - 2*zp_i.zq_i )        (s_ii kept exact fp32)
//
// pp tiles: wrapped diagonal (I,(I+d)%64), d=0..31 all I, d=32 for I<32 (2080
// tiles instead of 4096); each off-diagonal tile also emits COLUMN sums, which
// by symmetry are the row sums of the mirror tile. pq tiles: full 4096.
// Finalize: single kernel, last-block-done pattern (fixed-order final sum).

#define NROWS 8192
#define DDIM  128
#define EPSN  1e-8f

#define BM 128
#define BN 128
#define NBLK (NROWS / BM)                      // 64 row/col blocks

// SMEM: A (128x128 bf16 swizzled) + 2 x B buffers; 96KB -> 2 CTAs/SM
#define TILE_BYTES (BM * 256)                  // 32768
#define SMEM_TOTAL (3 * TILE_BYTES)            // 98304

#define PQ_CTAS 512                            // 64 I-blocks x 8 col groups
#define PP_CTAS 512                            // 64 I-blocks x 8 d groups
#define FBLOCKS 32

__device__ __nv_bfloat16 g_zp16[NROWS * DDIM];
__device__ __nv_bfloat16 g_zq16[NROWS * DDIM];
__device__ float g_sii[NROWS];
__device__ float g_rpart[8 * NROWS];           // pp row partials   [g][row]
__device__ float g_qpart[8 * NROWS];           // pq row partials   [c][row]
__device__ float g_cpart[32 * 2 * NROWS];      // pp col partials [d-1][wm][col]
__device__ float g_lpart[FBLOCKS];
__device__ int   g_fin_count;                  // zero-init at load; self-resetting

// ---------------------------------------------------------------------------
__device__ __forceinline__ uint32_t smem_u32(const void* p) {
    uint32_t a;
    asm("{ .reg .u64 t; cvta.to.shared.u64 t, %1; cvt.u32.u64 %0, t; }" : "=r"(a) : "l"(p));
    return a;
}
#define CP_COMMIT() asm volatile("cp.async.commit_group;" ::: "memory")
#define CP_WAIT0()  asm volatile("cp.async.wait_group 0;" ::: "memory")
#define CP_WAIT1()  asm volatile("cp.async.wait_group 1;" ::: "memory")

__device__ __forceinline__ float exp2x(float x) {   // exp(2x) = 2^(x * 2/ln2)
    float e;
    asm("ex2.approx.ftz.f32 %0, %1;" : "=f"(e) : "f"(x * 2.8853900817779268f));
    return e;
}

// cp.async a [128 rows x 128 k] bf16 tile into swizzled SMEM.
__device__ __forceinline__ void cp_tile(uint32_t sbase, const __nv_bfloat16* g,
                                        int row0, int tid) {
    #pragma unroll
    for (int i = 0; i < 8; i++) {
        int idx = i * 256 + tid;
        int r = idx >> 4;                 // 0..127
        int c = idx & 15;                 // 16B chunk
        uint32_t dst = sbase + (uint32_t)(r * 256 + ((c ^ (r & 7)) << 4));
        const void* src = g + (row0 + r) * DDIM + c * 8;
        asm volatile("cp.async.cg.shared.global [%0], [%1], 16;" :: "r"(dst), "l"(src));
    }
}

// ldmatrix x4: A fragment (m16 x k16) for rows r0..r0+15, k-step ks
__device__ __forceinline__ void lda_frag(uint32_t* a, uint32_t sbase, int r0,
                                         int ks, int lane) {
    int r = r0 + (lane & 15);
    int c = (2 * ks + (lane >> 4)) ^ (r & 7);
    uint32_t addr = sbase + (uint32_t)(r * 256 + c * 16);
    asm volatile("ldmatrix.sync.aligned.m8n8.x4.shared.b16 {%0,%1,%2,%3}, [%4];"
                 : "=r"(a[0]), "=r"(a[1]), "=r"(a[2]), "=r"(a[3]) : "r"(addr));
}

// ldmatrix x4: B fragments for TWO n-tiles (16 n-rows) at k-step ks.
__device__ __forceinline__ void ldb_frag(uint32_t* b, uint32_t sbase, int n0,
                                         int ks, int lane) {
    int g = lane >> 3;                    // 0..3
    int n = n0 + ((g >> 1) << 3) + (lane & 7);
    int c = (2 * ks + (g & 1)) ^ (n & 7);
    uint32_t addr = sbase + (uint32_t)(n * 256 + c * 16);
    asm volatile("ldmatrix.sync.aligned.m8n8.x4.shared.b16 {%0,%1,%2,%3}, [%4];"
                 : "=r"(b[0]), "=r"(b[1]), "=r"(b[2]), "=r"(b[3]) : "r"(addr));
}

__device__ __forceinline__ void mma16816(float* c, const uint32_t* a,
                                         const uint32_t* b) {
    asm volatile(
        "mma.sync.aligned.m16n8k16.row.col.f32.bf16.bf16.f32 "
        "{%0,%1,%2,%3}, {%4,%5,%6,%7}, {%8,%9}, {%0,%1,%2,%3};"
        : "+f"(c[0]), "+f"(c[1]), "+f"(c[2]), "+f"(c[3])
        : "r"(a[0]), "r"(a[1]), "r"(a[2]), "r"(a[3]), "r"(b[0]), "r"(b[1]));
}

// pp d-schedule: group g owns d = {4g..4g+3}; group 0 additionally d=32 (I<32).
__device__ __forceinline__ int pp_d(int g, int t) {
    return g ? (g * 4 + t) : (t < 4 ? t : 32);
}

// ---------------------------------------------------------------------------
// Kernel 1: warp-per-row fp32 normalize -> bf16 + exact fp32 diagonal dot.
// ---------------------------------------------------------------------------
__global__ __launch_bounds__(256) void normalize_kernel(
        const float* __restrict__ pred, const float* __restrict__ posv) {
    int w    = threadIdx.x >> 5;
    int lane = threadIdx.x & 31;
    int row  = blockIdx.x * 8 + w;

    float4 vp = reinterpret_cast<const float4*>(pred + row * DDIM)[lane];
    float4 vq = reinterpret_cast<const float4*>(posv + row * DDIM)[lane];

    float sp = vp.x*vp.x + vp.y*vp.y + vp.z*vp.z + vp.w*vp.w;
    float sq = vq.x*vq.x + vq.y*vq.y + vq.z*vq.z + vq.w*vq.w;
    #pragma unroll
    for (int o = 16; o > 0; o >>= 1) {
        sp += __shfl_xor_sync(0xffffffffu, sp, o);
        sq += __shfl_xor_sync(0xffffffffu, sq, o);
    }
    float rp = 1.0f / fmaxf(sqrtf(sp), EPSN);
    float rq = 1.0f / fmaxf(sqrtf(sq), EPSN);

    float4 zp = make_float4(vp.x*rp, vp.y*rp, vp.z*rp, vp.w*rp);
    float4 zq = make_float4(vq.x*rq, vq.y*rq, vq.z*rq, vq.w*rq);

    __nv_bfloat162* op = reinterpret_cast<__nv_bfloat162*>(g_zp16 + row * DDIM) + lane * 2;
    __nv_bfloat162* oq = reinterpret_cast<__nv_bfloat162*>(g_zq16 + row * DDIM) + lane * 2;
    op[0] = __floats2bfloat162_rn(zp.x, zp.y);
    op[1] = __floats2bfloat162_rn(zp.z, zp.w);
    oq[0] = __floats2bfloat162_rn(zq.x, zq.y);
    oq[1] = __floats2bfloat162_rn(zq.z, zq.w);

    float d = zp.x*zq.x + zp.y*zq.y + zp.z*zq.z + zp.w*zq.w;
    #pragma unroll
    for (int o = 16; o > 0; o >>= 1)
        d += __shfl_xor_sync(0xffffffffu, d, o);
    if (lane == 0) g_sii[row] = d;
}

// ---------------------------------------------------------------------------
// Kernel 2: merged pq + symmetric-pp HMMA GEMM with fused exp/row(+col) sums.
// bid < PQ_CTAS: pq role (I = bid>>3, c = bid&7): 8 zq tiles, row sums only.
// bid >= PQ_CTAS: pp role (I, g): 4-5 zp tiles (wrapped diagonal), row sums
//                 for block I + column sums for each target block (d>0).
// ---------------------------------------------------------------------------
__global__ __launch_bounds__(256, 2) void simclr_mma_kernel() {
    extern __shared__ char smem[];
    uint32_t sA = smem_u32(smem);
    uint32_t sB[2] = { sA + TILE_BYTES, sA + 2 * TILE_BYTES };

    int tid  = threadIdx.x;
    int wid  = tid >> 5, lane = tid & 31;
    int wm   = wid & 1;                  // M offset wm*64
    int wn   = wid >> 1;                 // N offset wn*32
    int bid  = blockIdx.x;

    bool isPQ = bid < PQ_CTAS;
    int I, g, nt;
    if (isPQ) { I = bid >> 3;              g = bid & 7; nt = 8; }
    else      { I = (bid - PQ_CTAS) >> 3;  g = (bid - PQ_CTAS) & 7;
                nt = (g == 0 && I < 32) ? 5 : 4; }
    int rowBase = I * BM;
    const __nv_bfloat16* src = isPQ ? g_zq16 : g_zp16;

    // B-tile first row for tile index t
    auto tile_row0 = [&](int t) -> int {
        if (isPQ) return (g * 8 + t) * BM;
        return ((I + pp_d(g, t)) & (NBLK - 1)) * BM;
    };

    // prologue: A + B tile 0 as one cp.async group
    cp_tile(sA, g_zp16, rowBase, tid);
    cp_tile(sB[0], src, tile_row0(0), tid);
    CP_COMMIT();

    float acc[4][4][4];
    float rsum[4][2];                    // per-lane row partials
    #pragma unroll
    for (int mi = 0; mi < 4; mi++) { rsum[mi][0] = 0.f; rsum[mi][1] = 0.f; }

    for (int j = 0; j < nt; j++) {
        int s = j & 1;
        __syncthreads();     // all warps done reading B[s^1]
        if (j + 1 < nt) {
            cp_tile(sB[s ^ 1], src, tile_row0(j + 1), tid);
            CP_COMMIT();
            CP_WAIT1();      // tile j resident
        } else {
            CP_WAIT0();
        }
        __syncthreads();     // tile j visible

        #pragma unroll
        for (int mi = 0; mi < 4; mi++)
            #pragma unroll
            for (int ni = 0; ni < 4; ni++)
                #pragma unroll
                for (int e = 0; e < 4; e++)
                    acc[mi][ni][e] = 0.f;

        #pragma unroll
        for (int ks = 0; ks < 8; ks++) {
            uint32_t a[4][4], b[2][4];
            #pragma unroll
            for (int mi = 0; mi < 4; mi++)
                lda_frag(a[mi], sA, wm * 64 + mi * 16, ks, lane);
            ldb_frag(b[0], sB[s], wn * 32 + 0,  ks, lane);
            ldb_frag(b[1], sB[s], wn * 32 + 16, ks, lane);
            #pragma unroll
            for (int mi = 0; mi < 4; mi++) {
                mma16816(acc[mi][0], a[mi], &b[0][0]);
                mma16816(acc[mi][1], a[mi], &b[0][2]);
                mma16816(acc[mi][2], a[mi], &b[1][0]);
                mma16816(acc[mi][3], a[mi], &b[1][2]);
            }
        }

        // epilogue: exp(2*s); row partials always, column partials for pp d>0.
        int d = isPQ ? 0 : pp_d(g, j);
        bool colout = (!isPQ) && (d > 0);

        float cp_[4][2];
        #pragma unroll
        for (int ni = 0; ni < 4; ni++) { cp_[ni][0] = 0.f; cp_[ni][1] = 0.f; }

        #pragma unroll
        for (int mi = 0; mi < 4; mi++) {
            #pragma unroll
            for (int ni = 0; ni < 4; ni++) {
                float e0 = exp2x(acc[mi][ni][0]);
                float e1 = exp2x(acc[mi][ni][1]);
                float e2 = exp2x(acc[mi][ni][2]);
                float e3 = exp2x(acc[mi][ni][3]);
                rsum[mi][0] += e0 + e1;
                rsum[mi][1] += e2 + e3;
                if (colout) {
                    cp_[ni][0] += e0 + e2;   // col C   (rows R, R+8)
                    cp_[ni][1] += e1 + e3;   // col C+1
                }
            }
        }

        if (colout) {
            // sum over the warp's 64 rows: butterfly across lane>>2 groups
            #pragma unroll
            for (int ni = 0; ni < 4; ni++)
                #pragma unroll
                for (int par = 0; par < 2; par++) {
                    float v = cp_[ni][par];
                    v += __shfl_xor_sync(0xffffffffu, v, 4);
                    v += __shfl_xor_sync(0xffffffffu, v, 8);
                    v += __shfl_xor_sync(0xffffffffu, v, 16);
                    cp_[ni][par] = v;
                }
            if (lane < 4) {
                int K = (I + d) & (NBLK - 1);
                float* dst = g_cpart + (uint32_t)((d - 1) * 2 + wm) * NROWS
                           + K * BM + wn * 32;
                #pragma unroll
                for (int ni = 0; ni < 4; ni++) {
                    dst[ni * 8 + 2 * lane + 0] = cp_[ni][0];
                    dst[ni * 8 + 2 * lane + 1] = cp_[ni][1];
                }
            }
        }
    }

    // lane-group reduction for rows (4 lanes share a row)
    #pragma unroll
    for (int mi = 0; mi < 4; mi++) {
        rsum[mi][0] += __shfl_xor_sync(0xffffffffu, rsum[mi][0], 1);
        rsum[mi][0] += __shfl_xor_sync(0xffffffffu, rsum[mi][0], 2);
        rsum[mi][1] += __shfl_xor_sync(0xffffffffu, rsum[mi][1], 1);
        rsum[mi][1] += __shfl_xor_sync(0xffffffffu, rsum[mi][1], 2);
    }

    // cross-warp (wn) reduction through SMEM, one deterministic write per row
    __syncthreads();
    float* red = (float*)smem;           // [128 rows][4 wn]
    if ((lane & 3) == 0) {
        #pragma unroll
        for (int mi = 0; mi < 4; mi++) {
            int r0 = wm * 64 + mi * 16 + (lane >> 2);
            red[r0 * 4 + wn]       = rsum[mi][0];
            red[(r0 + 8) * 4 + wn] = rsum[mi][1];
        }
    }
    __syncthreads();
    if (tid < BM) {
        float v = red[tid * 4 + 0] + red[tid * 4 + 1]
                + red[tid * 4 + 2] + red[tid * 4 + 3];
        float* outp = isPQ ? (g_qpart + (uint32_t)g * NROWS)
                           : (g_rpart + (uint32_t)g * NROWS);
        outp[rowBase + tid] = v;
    }
}

// ---------------------------------------------------------------------------
// Kernel 3: per-row loss + full reduction in ONE kernel (last-block-done).
// Per-block partial -> g_lpart[bid] (fixed slot); int ticket via atomicAdd;
// the last block sums g_lpart[0..31] IN FIXED ORDER (deterministic), writes
// the mean, and resets the ticket counter for the next graph replay.
// ---------------------------------------------------------------------------
__global__ __launch_bounds__(256) void finalize_kernel(float* __restrict__ out) {
    __shared__ float sh[256];
    __shared__ int   is_last;
    int tid = threadIdx.x;
    int i   = blockIdx.x * 256 + tid;
    const float diag_pp = expf(2.0f);

    float neg = -diag_pp;
    #pragma unroll
    for (int s = 0; s < 8; s++) neg += g_qpart[s * NROWS + i];
    #pragma unroll
    for (int s = 0; s < 8; s++) neg += g_rpart[s * NROWS + i];
    #pragma unroll
    for (int d = 1; d < 32; d++)
        neg += g_cpart[((d - 1) * 2 + 0) * NROWS + i]
             + g_cpart[((d - 1) * 2 + 1) * NROWS + i];
    if (i >= 32 * BM)   // d=32 slot only written for target blocks 32..63
        neg += g_cpart[(31 * 2 + 0) * NROWS + i]
             + g_cpart[(31 * 2 + 1) * NROWS + i];

    sh[tid] = logf(neg) - 2.0f * g_sii[i];
    __syncthreads();
    #pragma unroll
    for (int s = 128; s > 0; s >>= 1) {
        if (tid < s) sh[tid] += sh[tid + s];
        __syncthreads();
    }

    if (tid == 0) {
        g_lpart[blockIdx.x] = sh[0];
        __threadfence();
        int ticket = atomicAdd(&g_fin_count, 1);
        is_last = (ticket == FBLOCKS - 1);
    }
    __syncthreads();

    if (is_last && tid == 0) {
        float s = 0.f;
        #pragma unroll
        for (int b = 0; b < FBLOCKS; b++) s += g_lpart[b];   // fixed order
        out[0] = s / (float)NROWS;
        g_fin_count = 0;          // self-reset for next replay
    }
}

// ---------------------------------------------------------------------------
extern "C" void kernel_launch(void* const* d_in, const int* in_sizes, int n_in,
                              void* d_out, int out_size) {
    const float* pred     = (const float*)d_in[0];
    const float* positive = (const float*)d_in[1];
    float* out = (float*)d_out;

    cudaFuncSetAttribute(simclr_mma_kernel,
                         cudaFuncAttributeMaxDynamicSharedMemorySize, SMEM_TOTAL);

    normalize_kernel<<<NROWS / 8, 256>>>(pred, positive);

    simclr_mma_kernel<<<PQ_CTAS + PP_CTAS, 256, SMEM_TOTAL>>>();

    finalize_kernel<<<FBLOCKS, 256>>>(out);
}